// round 2
// baseline (speedup 1.0000x reference)
#include <cuda_runtime.h>

#define NNODES 50000

struct Params {
    float cL1[2], cR1[2], cE1[2];
    float W1[32], We1[32], b1s[16];
    float W2[32];
    float al2[2], ar2[2], aeWe2[2], We2[2];
    float b2s;
};

__device__ Params gP;
__device__ float  g_sumcap[NNODES];
__device__ float4 g_acc1[2 * NNODES];   // per (node,h): {S1, S2, s, pad}
__device__ float2 g_ft2[NNODES];        // layer-2 node features per head
__device__ float4 g_acc2[NNODES];       // per node: {num0, s0, num1, s1}
__device__ float  g_x2[NNODES];         // final scalar node feature

__device__ __forceinline__ void red_add_v4(float4* p, float a, float b, float c, float d) {
    asm volatile("red.global.add.v4.f32 [%0], {%1, %2, %3, %4};"
                 :: "l"(p), "f"(a), "f"(b), "f"(c), "f"(d) : "memory");
}

__device__ __forceinline__ float leaky(float v) { return v > 0.f ? v : 0.2f * v; }

// ---------------------------------------------------------------- zero scratch
__global__ void k_zero() {
    int i = blockIdx.x * blockDim.x + threadIdx.x;
    if (i < NNODES) {
        g_sumcap[i] = 0.f;
        g_acc2[i] = make_float4(0.f, 0.f, 0.f, 0.f);
    }
    if (i < 2 * NNODES) g_acc1[i] = make_float4(0.f, 0.f, 0.f, 0.f);
}

// ---------------------------------------------------------------- tiny param prep
__global__ void k_prep(const float* __restrict__ W1,  const float* __restrict__ We1,
                       const float* __restrict__ al1, const float* __restrict__ ar1,
                       const float* __restrict__ ae1, const float* __restrict__ b1,
                       const float* __restrict__ W2,  const float* __restrict__ We2,
                       const float* __restrict__ al2, const float* __restrict__ ar2,
                       const float* __restrict__ ae2, const float* __restrict__ b2) {
    if (threadIdx.x != 0 || blockIdx.x != 0) return;
    for (int h = 0; h < 2; h++) {
        float cl = 0.f, cr = 0.f, ce = 0.f;
        for (int d = 0; d < 16; d++) {
            cl += W1[h * 16 + d]  * al1[h * 16 + d];
            cr += W1[h * 16 + d]  * ar1[h * 16 + d];
            ce += We1[h * 16 + d] * ae1[h * 16 + d];
        }
        gP.cL1[h] = cl; gP.cR1[h] = cr; gP.cE1[h] = ce;
        gP.al2[h] = al2[h]; gP.ar2[h] = ar2[h];
        gP.aeWe2[h] = We2[h] * ae2[h]; gP.We2[h] = We2[h];
    }
    for (int i = 0; i < 32; i++) { gP.W1[i] = W1[i]; gP.We1[i] = We1[i]; gP.W2[i] = W2[i]; }
    for (int d = 0; d < 16; d++) gP.b1s[d] = b1[d] + b1[16 + d];
    gP.b2s = b2[0] + b2[1];
}

// ---------------------------------------------------------------- sum of incoming capacities
__global__ void k_sumcap(const int* __restrict__ dst, const float* __restrict__ cap, int E) {
    for (int e = blockIdx.x * blockDim.x + threadIdx.x; e < E; e += gridDim.x * blockDim.x)
        atomicAdd(&g_sumcap[dst[e]], cap[e]);
}

// ---------------------------------------------------------------- layer-1 edge pass
// logit[h] = sumcap[src]*cL + sumcap[dst]*cR + efeat*cE  (all bounded; softmax max-shift
// is mathematically a no-op, so accumulate unnormalized exp directly)
__global__ void k_l1_edge(const int* __restrict__ src, const int* __restrict__ dst,
                          const float* __restrict__ ef, int E) {
    float cL0 = gP.cL1[0], cR0 = gP.cR1[0], cE0 = gP.cE1[0];
    float cL1 = gP.cL1[1], cR1 = gP.cR1[1], cE1 = gP.cE1[1];
    for (int e = blockIdx.x * blockDim.x + threadIdx.x; e < E; e += gridDim.x * blockDim.x) {
        int s = src[e], d = dst[e];
        float f   = ef[e];
        float scs = __ldg(&g_sumcap[s]);
        float scd = __ldg(&g_sumcap[d]);
        float z0  = scs * cL0 + scd * cR0 + f * cE0;
        float ex0 = __expf(leaky(z0));
        float z1  = scs * cL1 + scd * cR1 + f * cE1;
        float ex1 = __expf(leaky(z1));
        red_add_v4(&g_acc1[2 * d],     ex0 * scs, ex0 * f, ex0, 0.f);
        red_add_v4(&g_acc1[2 * d + 1], ex1 * scs, ex1 * f, ex1, 0.f);
    }
}

// ---------------------------------------------------------------- layer-1 node pass
__global__ void k_l1_node() {
    int n = blockIdx.x * blockDim.x + threadIdx.x;
    if (n >= NNODES) return;
    float4 a0 = g_acc1[2 * n];
    float4 a1 = g_acc1[2 * n + 1];
    float i0 = 1.f / a0.z, i1 = 1.f / a1.z;
    float S10 = a0.x * i0, S20 = a0.y * i0;
    float S11 = a1.x * i1, S21 = a1.y * i1;
    float ft20 = 0.f, ft21 = 0.f;
#pragma unroll
    for (int d = 0; d < 16; d++) {
        float x = gP.W1[d] * S10 + gP.We1[d] * S20
                + gP.W1[16 + d] * S11 + gP.We1[16 + d] * S21 + gP.b1s[d];
        x = fmaxf(x, 0.f);
        ft20 += x * gP.W2[2 * d];
        ft21 += x * gP.W2[2 * d + 1];
    }
    g_ft2[n] = make_float2(ft20, ft21);
}

// ---------------------------------------------------------------- layer-2 edge pass (one v4 red / edge)
__global__ void k_l2_edge(const int* __restrict__ src, const int* __restrict__ dst,
                          const float* __restrict__ ef, int E) {
    float al20 = gP.al2[0], ar20 = gP.ar2[0], aeWe20 = gP.aeWe2[0], We20 = gP.We2[0];
    float al21 = gP.al2[1], ar21 = gP.ar2[1], aeWe21 = gP.aeWe2[1], We21 = gP.We2[1];
    for (int e = blockIdx.x * blockDim.x + threadIdx.x; e < E; e += gridDim.x * blockDim.x) {
        int s = src[e], d = dst[e];
        float f = ef[e];
        float2 fs = __ldg(&g_ft2[s]);
        float2 fd = __ldg(&g_ft2[d]);

        float z0  = fs.x * al20 + fd.x * ar20 + f * aeWe20;
        float ex0 = __expf(leaky(z0));
        float n0  = (fs.x + f * We20) * ex0;

        float z1  = fs.y * al21 + fd.y * ar21 + f * aeWe21;
        float ex1 = __expf(leaky(z1));
        float n1  = (fs.y + f * We21) * ex1;

        red_add_v4(&g_acc2[d], n0, ex0, n1, ex1);
    }
}

// ---------------------------------------------------------------- layer-2 node pass
__global__ void k_l2_node() {
    int n = blockIdx.x * blockDim.x + threadIdx.x;
    if (n >= NNODES) return;
    float4 a = g_acc2[n];
    g_x2[n] = a.x / a.y + a.z / a.w + gP.b2s;
}

// ---------------------------------------------------------------- output edge pass
__global__ void k_out(const int* __restrict__ src, const int* __restrict__ dst,
                      float* __restrict__ out, int E) {
    for (int e = blockIdx.x * blockDim.x + threadIdx.x; e < E; e += gridDim.x * blockDim.x)
        out[e] = sqrtf(__ldg(&g_x2[src[e]]) * __ldg(&g_x2[dst[e]]));
}

extern "C" void kernel_launch(void* const* d_in, const int* in_sizes, int n_in,
                              void* d_out, int out_size) {
    const int*   src = (const int*)d_in[0];
    const int*   dst = (const int*)d_in[1];
    const float* cap = (const float*)d_in[2];
    const float* ef  = (const float*)d_in[3];
    const float* W1  = (const float*)d_in[4];
    const float* We1 = (const float*)d_in[5];
    const float* al1 = (const float*)d_in[6];
    const float* ar1 = (const float*)d_in[7];
    const float* ae1 = (const float*)d_in[8];
    const float* b1  = (const float*)d_in[9];
    const float* W2  = (const float*)d_in[10];
    const float* We2 = (const float*)d_in[11];
    const float* al2 = (const float*)d_in[12];
    const float* ar2 = (const float*)d_in[13];
    const float* ae2 = (const float*)d_in[14];
    const float* b2  = (const float*)d_in[15];
    float* out = (float*)d_out;

    int E = in_sizes[0];
    const int TB = 256;
    int gbN  = (NNODES + TB - 1) / TB;
    int gbN2 = (2 * NNODES + TB - 1) / TB;
    int gbE  = 148 * 8;   // grid-stride, ~2 waves of 4-CTA occupancy

    k_zero<<<gbN2, TB>>>();
    k_prep<<<1, 32>>>(W1, We1, al1, ar1, ae1, b1, W2, We2, al2, ar2, ae2, b2);
    k_sumcap<<<gbE, TB>>>(dst, cap, E);
    k_l1_edge<<<gbE, TB>>>(src, dst, ef, E);
    k_l1_node<<<gbN, TB>>>();
    k_l2_edge<<<gbE, TB>>>(src, dst, ef, E);
    k_l2_node<<<gbN, TB>>>();
    k_out<<<gbE, TB>>>(src, dst, out, E);
}

// round 3
// speedup vs baseline: 1.1542x; 1.1542x over previous
#include <cuda_runtime.h>
#include <cuda_fp16.h>

#define NNODES 50000
#define SMEM_BYTES 200000   // 50000 floats / 50000 half2

struct Params {
    float cL1[2], cR1[2], cE1[2];
    float W1[32], We1[32], b1s[16];
    float W2[32];
    float al2[2], ar2[2], aeWe2[2], We2[2];
    float b2s;
};

__device__ Params gP;
__device__ __align__(16) float   g_sumcap[NNODES];
__device__ __align__(32) float4  g_acc1[2 * NNODES]; // node n: [S1_0,S2_0,s_0,S1_1][S2_1,s_1,-,-]
__device__ __align__(16) __half2 g_ft2h[NNODES];     // layer-2 node features (fp16 per head)
__device__ __align__(16) float4  g_acc2[NNODES];     // {num0, s0, num1, s1}
__device__ __align__(16) float   g_x2[NNODES];

__device__ __forceinline__ void red_add_v4(float4* p, float a, float b, float c, float d) {
    asm volatile("red.global.add.v4.f32 [%0], {%1, %2, %3, %4};"
                 :: "l"(p), "f"(a), "f"(b), "f"(c), "f"(d) : "memory");
}
__device__ __forceinline__ void red_add_v2(float2* p, float a, float b) {
    asm volatile("red.global.add.v2.f32 [%0], {%1, %2};"
                 :: "l"(p), "f"(a), "f"(b) : "memory");
}
__device__ __forceinline__ float leaky(float v) { return v > 0.f ? v : 0.2f * v; }

// ---------------------------------------------------------------- init: zero scratch + param prep
__global__ void k_init(const float* __restrict__ W1,  const float* __restrict__ We1,
                       const float* __restrict__ al1, const float* __restrict__ ar1,
                       const float* __restrict__ ae1, const float* __restrict__ b1,
                       const float* __restrict__ W2,  const float* __restrict__ We2,
                       const float* __restrict__ al2, const float* __restrict__ ar2,
                       const float* __restrict__ ae2, const float* __restrict__ b2) {
    int i = blockIdx.x * blockDim.x + threadIdx.x;
    if (i < NNODES) {
        g_sumcap[i] = 0.f;
        g_acc2[i] = make_float4(0.f, 0.f, 0.f, 0.f);
    }
    if (i < 2 * NNODES) g_acc1[i] = make_float4(0.f, 0.f, 0.f, 0.f);
    if (i == 0) {
        for (int h = 0; h < 2; h++) {
            float cl = 0.f, cr = 0.f, ce = 0.f;
            for (int d = 0; d < 16; d++) {
                cl += W1[h * 16 + d]  * al1[h * 16 + d];
                cr += W1[h * 16 + d]  * ar1[h * 16 + d];
                ce += We1[h * 16 + d] * ae1[h * 16 + d];
            }
            gP.cL1[h] = cl; gP.cR1[h] = cr; gP.cE1[h] = ce;
            gP.al2[h] = al2[h]; gP.ar2[h] = ar2[h];
            gP.aeWe2[h] = We2[h] * ae2[h]; gP.We2[h] = We2[h];
        }
        for (int k = 0; k < 32; k++) { gP.W1[k] = W1[k]; gP.We1[k] = We1[k]; gP.W2[k] = W2[k]; }
        for (int d = 0; d < 16; d++) gP.b1s[d] = b1[d] + b1[16 + d];
        gP.b2s = b2[0] + b2[1];
    }
}

// ---------------------------------------------------------------- sum of incoming capacities
__global__ void k_sumcap(const int* __restrict__ dst, const float* __restrict__ cap, int E) {
    for (int e = blockIdx.x * blockDim.x + threadIdx.x; e < E; e += gridDim.x * blockDim.x)
        atomicAdd(&g_sumcap[dst[e]], cap[e]);
}

// ---------------------------------------------------------------- smem preload helper (fp32/any 16B)
__device__ __forceinline__ void preload16(void* smem, const void* gmem, int bytes) {
    float4* s4 = (float4*)smem;
    const float4* g4 = (const float4*)gmem;
    int n = bytes >> 4;
    for (int i = threadIdx.x; i < n; i += blockDim.x) s4[i] = g4[i];
    __syncthreads();
}

// ---------------------------------------------------------------- layer-1 edge pass (smem-cached sumcap)
__global__ void k_l1_edge(const int* __restrict__ src, const int* __restrict__ dst,
                          const float* __restrict__ ef, int E) {
    extern __shared__ float s_sc[];
    preload16(s_sc, g_sumcap, NNODES * 4);
    float cL0 = gP.cL1[0], cR0 = gP.cR1[0], cE0 = gP.cE1[0];
    float cL1 = gP.cL1[1], cR1 = gP.cR1[1], cE1 = gP.cE1[1];

    int gtid = blockIdx.x * blockDim.x + threadIdx.x;
    int gstride = gridDim.x * blockDim.x;
    int nvec = E >> 2;
    const int4*   src4 = (const int4*)src;
    const int4*   dst4 = (const int4*)dst;
    const float4* ef4  = (const float4*)ef;

    for (int i = gtid; i < nvec; i += gstride) {
        int4 s4 = src4[i], d4 = dst4[i];
        float4 f4 = ef4[i];
#pragma unroll
        for (int k = 0; k < 4; k++) {
            int s = (&s4.x)[k], d = (&d4.x)[k];
            float f = (&f4.x)[k];
            float scs = s_sc[s], scd = s_sc[d];
            float ex0 = __expf(leaky(scs * cL0 + scd * cR0 + f * cE0));
            float ex1 = __expf(leaky(scs * cL1 + scd * cR1 + f * cE1));
            red_add_v4(&g_acc1[2 * d], ex0 * scs, ex0 * f, ex0, ex1 * scs);
            red_add_v2((float2*)&g_acc1[2 * d + 1], ex1 * f, ex1);
        }
    }
    for (int e = (nvec << 2) + gtid; e < E; e += gstride) {
        int s = src[e], d = dst[e];
        float f = ef[e];
        float scs = s_sc[s], scd = s_sc[d];
        float ex0 = __expf(leaky(scs * cL0 + scd * cR0 + f * cE0));
        float ex1 = __expf(leaky(scs * cL1 + scd * cR1 + f * cE1));
        red_add_v4(&g_acc1[2 * d], ex0 * scs, ex0 * f, ex0, ex1 * scs);
        red_add_v2((float2*)&g_acc1[2 * d + 1], ex1 * f, ex1);
    }
}

// ---------------------------------------------------------------- layer-1 node pass -> fp16 ft2
__global__ void k_l1_node() {
    int n = blockIdx.x * blockDim.x + threadIdx.x;
    if (n >= NNODES) return;
    float4 A = g_acc1[2 * n];
    float4 B = g_acc1[2 * n + 1];
    float i0 = 1.f / A.z, i1 = 1.f / B.y;
    float S10 = A.x * i0, S20 = A.y * i0;
    float S11 = A.w * i1, S21 = B.x * i1;
    float ft20 = 0.f, ft21 = 0.f;
#pragma unroll
    for (int d = 0; d < 16; d++) {
        float x = gP.W1[d] * S10 + gP.We1[d] * S20
                + gP.W1[16 + d] * S11 + gP.We1[16 + d] * S21 + gP.b1s[d];
        x = fmaxf(x, 0.f);
        ft20 += x * gP.W2[2 * d];
        ft21 += x * gP.W2[2 * d + 1];
    }
    g_ft2h[n] = __floats2half2_rn(ft20, ft21);
}

// ---------------------------------------------------------------- layer-2 edge pass (smem-cached fp16 ft2)
__global__ void k_l2_edge(const int* __restrict__ src, const int* __restrict__ dst,
                          const float* __restrict__ ef, int E) {
    extern __shared__ __half2 s_ft[];
    preload16(s_ft, g_ft2h, NNODES * 4);
    float al20 = gP.al2[0], ar20 = gP.ar2[0], aeWe20 = gP.aeWe2[0], We20 = gP.We2[0];
    float al21 = gP.al2[1], ar21 = gP.ar2[1], aeWe21 = gP.aeWe2[1], We21 = gP.We2[1];

    int gtid = blockIdx.x * blockDim.x + threadIdx.x;
    int gstride = gridDim.x * blockDim.x;
    int nvec = E >> 2;
    const int4*   src4 = (const int4*)src;
    const int4*   dst4 = (const int4*)dst;
    const float4* ef4  = (const float4*)ef;

    for (int i = gtid; i < nvec; i += gstride) {
        int4 s4 = src4[i], d4 = dst4[i];
        float4 f4 = ef4[i];
#pragma unroll
        for (int k = 0; k < 4; k++) {
            int s = (&s4.x)[k], d = (&d4.x)[k];
            float f = (&f4.x)[k];
            float2 fs = __half22float2(s_ft[s]);
            float2 fd = __half22float2(s_ft[d]);
            float ex0 = __expf(leaky(fs.x * al20 + fd.x * ar20 + f * aeWe20));
            float n0  = (fs.x + f * We20) * ex0;
            float ex1 = __expf(leaky(fs.y * al21 + fd.y * ar21 + f * aeWe21));
            float n1  = (fs.y + f * We21) * ex1;
            red_add_v4(&g_acc2[d], n0, ex0, n1, ex1);
        }
    }
    for (int e = (nvec << 2) + gtid; e < E; e += gstride) {
        int s = src[e], d = dst[e];
        float f = ef[e];
        float2 fs = __half22float2(s_ft[s]);
        float2 fd = __half22float2(s_ft[d]);
        float ex0 = __expf(leaky(fs.x * al20 + fd.x * ar20 + f * aeWe20));
        float n0  = (fs.x + f * We20) * ex0;
        float ex1 = __expf(leaky(fs.y * al21 + fd.y * ar21 + f * aeWe21));
        float n1  = (fs.y + f * We21) * ex1;
        red_add_v4(&g_acc2[d], n0, ex0, n1, ex1);
    }
}

// ---------------------------------------------------------------- layer-2 node pass
__global__ void k_l2_node() {
    int n = blockIdx.x * blockDim.x + threadIdx.x;
    if (n >= NNODES) return;
    float4 a = g_acc2[n];
    g_x2[n] = a.x / a.y + a.z / a.w + gP.b2s;
}

// ---------------------------------------------------------------- output edge pass (smem-cached x2)
__global__ void k_out(const int* __restrict__ src, const int* __restrict__ dst,
                      float* __restrict__ out, int E) {
    extern __shared__ float s_x[];
    preload16(s_x, g_x2, NNODES * 4);

    int gtid = blockIdx.x * blockDim.x + threadIdx.x;
    int gstride = gridDim.x * blockDim.x;
    int nvec = E >> 2;
    const int4* src4 = (const int4*)src;
    const int4* dst4 = (const int4*)dst;
    float4* out4 = (float4*)out;

    for (int i = gtid; i < nvec; i += gstride) {
        int4 s4 = src4[i], d4 = dst4[i];
        float4 o;
        o.x = sqrtf(s_x[s4.x] * s_x[d4.x]);
        o.y = sqrtf(s_x[s4.y] * s_x[d4.y]);
        o.z = sqrtf(s_x[s4.z] * s_x[d4.z]);
        o.w = sqrtf(s_x[s4.w] * s_x[d4.w]);
        out4[i] = o;
    }
    for (int e = (nvec << 2) + gtid; e < E; e += gstride)
        out[e] = sqrtf(s_x[src[e]] * s_x[dst[e]]);
}

extern "C" void kernel_launch(void* const* d_in, const int* in_sizes, int n_in,
                              void* d_out, int out_size) {
    const int*   src = (const int*)d_in[0];
    const int*   dst = (const int*)d_in[1];
    const float* cap = (const float*)d_in[2];
    const float* ef  = (const float*)d_in[3];
    const float* W1  = (const float*)d_in[4];
    const float* We1 = (const float*)d_in[5];
    const float* al1 = (const float*)d_in[6];
    const float* ar1 = (const float*)d_in[7];
    const float* ae1 = (const float*)d_in[8];
    const float* b1  = (const float*)d_in[9];
    const float* W2  = (const float*)d_in[10];
    const float* We2 = (const float*)d_in[11];
    const float* al2 = (const float*)d_in[12];
    const float* ar2 = (const float*)d_in[13];
    const float* ae2 = (const float*)d_in[14];
    const float* b2  = (const float*)d_in[15];
    float* out = (float*)d_out;

    int E = in_sizes[0];
    const int TB = 256;
    int gbN2 = (2 * NNODES + TB - 1) / TB;
    int gbN  = (NNODES + TB - 1) / TB;

    static bool attr_done = false;
    if (!attr_done) {
        cudaFuncSetAttribute(k_l1_edge, cudaFuncAttributeMaxDynamicSharedMemorySize, SMEM_BYTES);
        cudaFuncSetAttribute(k_l2_edge, cudaFuncAttributeMaxDynamicSharedMemorySize, SMEM_BYTES);
        cudaFuncSetAttribute(k_out,     cudaFuncAttributeMaxDynamicSharedMemorySize, SMEM_BYTES);
        attr_done = true;
    }

    k_init<<<gbN2, TB>>>(W1, We1, al1, ar1, ae1, b1, W2, We2, al2, ar2, ae2, b2);
    k_sumcap<<<148 * 8, TB>>>(dst, cap, E);
    k_l1_edge<<<148, 1024, SMEM_BYTES>>>(src, dst, ef, E);
    k_l1_node<<<gbN, TB>>>();
    k_l2_edge<<<148, 1024, SMEM_BYTES>>>(src, dst, ef, E);
    k_l2_node<<<gbN, TB>>>();
    k_out<<<148, 1024, SMEM_BYTES>>>(src, dst, out, E);
}